// round 5
// baseline (speedup 1.0000x reference)
#include <cuda_runtime.h>

// Problem constants (fixed by reference_code)
#define IN_F   256
#define N_ASS  4096
#define OUT_F  256
#define BATCH  128
#define ASS0   IN_F            // 256  : first associative neuron index
#define OUT0   (IN_F + N_ASS)  // 4352 : first output neuron index

// ELL strides (padded gather lists keyed by destination).
// hop1 in-degree ~ Bin(256,0.05): mean 12.8, sd 3.5  -> 64 is ~14 sigma safe
// hop2 in-degree ~ Bin(4096,0.05): mean 204.8, sd 13.9 -> 384 is ~13 sigma safe
#define ELL1_S 64
#define ELL2_S 384

// Device scratch (no runtime allocation allowed)
__device__ float g_xT  [IN_F  * BATCH];     // x transposed: [in_f][batch]
__device__ float g_HT  [N_ASS * BATCH];     // hidden acts transposed: [assoc][batch]
__device__ int   g_cnt1[N_ASS];             // per-assoc in-degree counters
__device__ int   g_cnt2[OUT_F];             // per-output in-degree counters
__device__ int   g_e1src[N_ASS * ELL1_S];   // hop1 ELL: src input index
__device__ float g_e1w  [N_ASS * ELL1_S];   // hop1 ELL: edge weight
__device__ int   g_e2src[OUT_F * ELL2_S];   // hop2 ELL: src assoc index (0-based)
__device__ float g_e2w  [OUT_F * ELL2_S];   // hop2 ELL: edge weight

// ---------------------------------------------------------------------------
// Kernel 1: zero the degree counters and transpose x -> xT.
// 32768 threads covers everything in one pass.
// ---------------------------------------------------------------------------
__global__ void prep_kernel(const float* __restrict__ x) {
    int tid = blockIdx.x * blockDim.x + threadIdx.x;
    if (tid < N_ASS) g_cnt1[tid] = 0;
    if (tid < OUT_F) g_cnt2[tid] = 0;
    if (tid < BATCH * IN_F) {
        int b = tid >> 8;          // / IN_F
        int i = tid & (IN_F - 1);  // % IN_F
        g_xT[i * BATCH + b] = x[tid];
    }
}

// ---------------------------------------------------------------------------
// Kernel 2: bucket hop-1 edges by destination (ELL append via atomic slot).
// ---------------------------------------------------------------------------
__global__ void build1_kernel(const int* __restrict__ src,
                              const int* __restrict__ dst,
                              const float* __restrict__ w, int E) {
    int e = blockIdx.x * blockDim.x + threadIdx.x;
    if (e < E) {
        int d = dst[e] - ASS0;
        int slot = atomicAdd(&g_cnt1[d], 1);
        if (slot < ELL1_S) {
            g_e1src[d * ELL1_S + slot] = src[e];
            g_e1w  [d * ELL1_S + slot] = w[e];
        }
    }
}

// ---------------------------------------------------------------------------
// Kernel 3: bucket hop-2 edges by destination, keeping ONLY edges that reach
// an output neuron (dst >= OUT0). Assoc-to-assoc edges never affect the
// result (acc2 at associative neurons is never read by the reference).
// ---------------------------------------------------------------------------
__global__ void build2_kernel(const int* __restrict__ src,
                              const int* __restrict__ dst,
                              const float* __restrict__ w, int E) {
    int e = blockIdx.x * blockDim.x + threadIdx.x;
    if (e < E) {
        int d = dst[e];
        if (d >= OUT0) {
            int o = d - OUT0;
            int slot = atomicAdd(&g_cnt2[o], 1);
            if (slot < ELL2_S) {
                g_e2src[o * ELL2_S + slot] = src[e] - ASS0;
                g_e2w  [o * ELL2_S + slot] = w[e];
            }
        }
    }
}

// ---------------------------------------------------------------------------
// Kernel 4 (hop 1): one warp per associative neuron.
// HT[a][:] = sum_j w_j * xT[src_j][:]     (lane covers 4 batch elements)
// xT is 128 KB -> L1-resident; loads are 512B fully-coalesced rows.
// ---------------------------------------------------------------------------
__global__ void __launch_bounds__(256)
hop1_kernel() {
    int warp = (blockIdx.x * blockDim.x + threadIdx.x) >> 5;  // 0..4095
    int lane = threadIdx.x & 31;
    int deg  = g_cnt1[warp];
    const int base = warp * ELL1_S;

    float4 acc = make_float4(0.f, 0.f, 0.f, 0.f);
    for (int j = 0; j < deg; j++) {
        int   s  = g_e1src[base + j];
        float wv = g_e1w  [base + j];
        float4 xv = *reinterpret_cast<const float4*>(&g_xT[s * BATCH + lane * 4]);
        acc.x += wv * xv.x;
        acc.y += wv * xv.y;
        acc.z += wv * xv.z;
        acc.w += wv * xv.w;
    }
    *reinterpret_cast<float4*>(&g_HT[warp * BATCH + lane * 4]) = acc;
}

// ---------------------------------------------------------------------------
// Kernel 5 (hop 2): one CTA (8 warps) per output neuron.
// Warps split the ~205 incoming edges, partial sums reduced through smem,
// then the batch column is written (transposed) into out[b][o].
// Every element of d_out is written -> no zero kernel needed.
// ---------------------------------------------------------------------------
__global__ void __launch_bounds__(256)
hop2_kernel(float* __restrict__ out) {
    __shared__ float red[8][BATCH];
    const int o    = blockIdx.x;
    const int warp = threadIdx.x >> 5;
    const int lane = threadIdx.x & 31;
    const int deg  = g_cnt2[o];
    const int base = o * ELL2_S;

    float4 acc = make_float4(0.f, 0.f, 0.f, 0.f);
    for (int j = warp; j < deg; j += 8) {
        int   s  = g_e2src[base + j];
        float wv = g_e2w  [base + j];
        float4 hv = *reinterpret_cast<const float4*>(&g_HT[s * BATCH + lane * 4]);
        acc.x += wv * hv.x;
        acc.y += wv * hv.y;
        acc.z += wv * hv.z;
        acc.w += wv * hv.w;
    }
    *reinterpret_cast<float4*>(&red[warp][lane * 4]) = acc;
    __syncthreads();

    if (threadIdx.x < BATCH) {
        float v = 0.f;
        #pragma unroll
        for (int wq = 0; wq < 8; wq++) v += red[wq][threadIdx.x];
        out[threadIdx.x * OUT_F + o] = v;   // out[b][o]
    }
}

// ---------------------------------------------------------------------------
// Launch
// ---------------------------------------------------------------------------
extern "C" void kernel_launch(void* const* d_in, const int* in_sizes, int n_in,
                              void* d_out, int out_size) {
    const float* x       = (const float*)d_in[0];  // [128, 256]
    const float* w_in    = (const float*)d_in[1];  // [E_in]
    const float* w_ass   = (const float*)d_in[2];  // [E_ass]
    const int*   in_src  = (const int*)  d_in[3];
    const int*   in_dst  = (const int*)  d_in[4];
    const int*   ass_src = (const int*)  d_in[5];
    const int*   ass_dst = (const int*)  d_in[6];

    const int E_in  = in_sizes[1];
    const int E_ass = in_sizes[2];
    float* out = (float*)d_out;

    prep_kernel  <<<(BATCH * IN_F + 255) / 256, 256>>>(x);
    build1_kernel<<<(E_in  + 255) / 256, 256>>>(in_src,  in_dst,  w_in,  E_in);
    build2_kernel<<<(E_ass + 255) / 256, 256>>>(ass_src, ass_dst, w_ass, E_ass);
    hop1_kernel  <<<(N_ASS * 32) / 256, 256>>>();          // 512 CTAs, 1 warp/assoc
    hop2_kernel  <<<OUT_F, 256>>>(out);                    // 256 CTAs, 1 CTA/output
}

// round 6
// speedup vs baseline: 1.0216x; 1.0216x over previous
#include <cuda_runtime.h>

// Problem constants (fixed by reference_code)
#define IN_F   256
#define N_ASS  4096
#define OUT_F  256
#define BATCH  128
#define ASS0   IN_F            // 256  : first associative neuron index
#define OUT0   (IN_F + N_ASS)  // 4352 : first output neuron index

// ELL strides (padded gather lists keyed by destination).
// hop1 in-degree ~ Bin(256,0.05): mean 12.8, sd 3.5  -> 64 is ~14 sigma safe
// hop2 in-degree ~ Bin(4096,0.05): mean 204.8, sd 13.9 -> 384 is ~13 sigma safe
#define ELL1_S 64
#define ELL2_S 384

// Device scratch (no runtime allocation allowed). Zero-initialized at load;
// the hop kernels re-zero the counters after consuming them, so every graph
// replay sees counters == 0 on entry to the build kernel.
__device__ float g_xT  [IN_F  * BATCH];     // x transposed: [in_f][batch]
__device__ float g_HT  [N_ASS * BATCH];     // hidden acts transposed
__device__ int   g_cnt1[N_ASS];             // per-assoc in-degree counters
__device__ int   g_cnt2[OUT_F];             // per-output in-degree counters
__device__ int   g_e1src[N_ASS * ELL1_S];
__device__ float g_e1w  [N_ASS * ELL1_S];
__device__ int   g_e2src[OUT_F * ELL2_S];
__device__ float g_e2w  [OUT_F * ELL2_S];

// ---------------------------------------------------------------------------
// Kernel A (fused): transpose x -> xT, bucket hop1 edges, bucket hop2 edges
// (keeping only dst >= OUT0; assoc->assoc edges never reach the output).
// All three tasks are independent; counters arrive already zeroed.
// ---------------------------------------------------------------------------
__global__ void __launch_bounds__(256)
build_kernel(const float* __restrict__ x,
             const int* __restrict__ in_src, const int* __restrict__ in_dst,
             const float* __restrict__ w_in, int E_in,
             const int* __restrict__ ass_src, const int* __restrict__ ass_dst,
             const float* __restrict__ w_ass, int E_ass) {
    const int t = blockIdx.x * blockDim.x + threadIdx.x;

    // --- transpose x (32768 elems) ---
    if (t < BATCH * IN_F) {
        int b = t >> 8;          // / IN_F
        int i = t & (IN_F - 1);  // % IN_F
        g_xT[i * BATCH + b] = x[t];
    }

    const int e = t * 4;

    // --- hop1 bucketing (vectorized 4 edges/thread) ---
    if (e + 4 <= E_in) {
        int4   s4 = *reinterpret_cast<const int4*>  (in_src + e);
        int4   d4 = *reinterpret_cast<const int4*>  (in_dst + e);
        float4 w4 = *reinterpret_cast<const float4*>(w_in   + e);
        #pragma unroll
        for (int k = 0; k < 4; k++) {
            int   s = (&s4.x)[k];
            int   d = (&d4.x)[k] - ASS0;
            float w = (&w4.x)[k];
            int slot = atomicAdd(&g_cnt1[d], 1);
            if (slot < ELL1_S) {
                g_e1src[d * ELL1_S + slot] = s;
                g_e1w  [d * ELL1_S + slot] = w;
            }
        }
    } else if (e < E_in) {
        for (int k = e; k < E_in; k++) {
            int d = in_dst[k] - ASS0;
            int slot = atomicAdd(&g_cnt1[d], 1);
            if (slot < ELL1_S) {
                g_e1src[d * ELL1_S + slot] = in_src[k];
                g_e1w  [d * ELL1_S + slot] = w_in[k];
            }
        }
    }

    // --- hop2 bucketing: scan dst vectorized, fetch src/w only for kept ---
    if (e + 4 <= E_ass) {
        int4 d4 = *reinterpret_cast<const int4*>(ass_dst + e);
        #pragma unroll
        for (int k = 0; k < 4; k++) {
            int d = (&d4.x)[k];
            if (d >= OUT0) {
                int o = d - OUT0;
                int slot = atomicAdd(&g_cnt2[o], 1);
                if (slot < ELL2_S) {
                    g_e2src[o * ELL2_S + slot] = ass_src[e + k] - ASS0;
                    g_e2w  [o * ELL2_S + slot] = w_ass[e + k];
                }
            }
        }
    } else if (e < E_ass) {
        for (int k = e; k < E_ass; k++) {
            int d = ass_dst[k];
            if (d >= OUT0) {
                int o = d - OUT0;
                int slot = atomicAdd(&g_cnt2[o], 1);
                if (slot < ELL2_S) {
                    g_e2src[o * ELL2_S + slot] = ass_src[k] - ASS0;
                    g_e2w  [o * ELL2_S + slot] = w_ass[k];
                }
            }
        }
    }
}

// ---------------------------------------------------------------------------
// Kernel B (hop 1): one warp per associative neuron.
// Edges consumed in aligned groups of 4: one int4 + one float4 uniform load,
// then 4 INDEPENDENT 512B row gathers in flight (MLP=4 vs the serial chain
// that left the old version at issue=19%). Resets g_cnt1 for the next replay.
// ---------------------------------------------------------------------------
__global__ void __launch_bounds__(256)
hop1_kernel() {
    const int warp = (blockIdx.x * blockDim.x + threadIdx.x) >> 5;  // 0..4095
    const int lane = threadIdx.x & 31;
    int deg = g_cnt1[warp];
    __syncwarp();
    if (lane == 0) g_cnt1[warp] = 0;   // consume-and-reset (all lanes read first)
    deg = min(deg, ELL1_S);
    const int base = warp * ELL1_S;    // multiple of 4 -> int4-aligned groups

    float4 acc = make_float4(0.f, 0.f, 0.f, 0.f);
    int j = 0;
    for (; j + 4 <= deg; j += 4) {
        int4   s4 = *reinterpret_cast<const int4*>  (&g_e1src[base + j]);
        float4 w4 = *reinterpret_cast<const float4*>(&g_e1w  [base + j]);
        float4 r0 = *reinterpret_cast<const float4*>(&g_xT[s4.x * BATCH + lane * 4]);
        float4 r1 = *reinterpret_cast<const float4*>(&g_xT[s4.y * BATCH + lane * 4]);
        float4 r2 = *reinterpret_cast<const float4*>(&g_xT[s4.z * BATCH + lane * 4]);
        float4 r3 = *reinterpret_cast<const float4*>(&g_xT[s4.w * BATCH + lane * 4]);
        acc.x += w4.x * r0.x + w4.y * r1.x + w4.z * r2.x + w4.w * r3.x;
        acc.y += w4.x * r0.y + w4.y * r1.y + w4.z * r2.y + w4.w * r3.y;
        acc.z += w4.x * r0.z + w4.y * r1.z + w4.z * r2.z + w4.w * r3.z;
        acc.w += w4.x * r0.w + w4.y * r1.w + w4.z * r2.w + w4.w * r3.w;
    }
    for (; j < deg; j++) {
        int   s = g_e1src[base + j];
        float w = g_e1w  [base + j];
        float4 r = *reinterpret_cast<const float4*>(&g_xT[s * BATCH + lane * 4]);
        acc.x += w * r.x; acc.y += w * r.y; acc.z += w * r.z; acc.w += w * r.w;
    }
    *reinterpret_cast<float4*>(&g_HT[warp * BATCH + lane * 4]) = acc;
}

// ---------------------------------------------------------------------------
// Kernel C (hop 2): one CTA of 16 warps per output neuron.
// Warp g consumes aligned 4-edge groups [4*(g+16k), +4): int4/float4 edge
// loads + 4 independent HT row gathers. Smem tree-reduce, write out[b][o].
// Every out element written -> no zero pass. Resets g_cnt2.
// ---------------------------------------------------------------------------
__global__ void __launch_bounds__(512)
hop2_kernel(float* __restrict__ out) {
    __shared__ float red[16][BATCH];
    const int o    = blockIdx.x;
    const int warp = threadIdx.x >> 5;
    const int lane = threadIdx.x & 31;
    int deg = min(g_cnt2[o], ELL2_S);
    __syncthreads();                       // all reads of the counter done
    if (threadIdx.x == 0) g_cnt2[o] = 0;   // consume-and-reset
    const int base = o * ELL2_S;           // multiple of 4

    float4 acc = make_float4(0.f, 0.f, 0.f, 0.f);
    for (int g = warp; ; g += 16) {
        int j = g * 4;
        if (j >= deg) break;
        int rem = deg - j;
        int4   s4 = *reinterpret_cast<const int4*>  (&g_e2src[base + j]);
        float4 w4 = *reinterpret_cast<const float4*>(&g_e2w  [base + j]);
        {
            float4 r = *reinterpret_cast<const float4*>(&g_HT[s4.x * BATCH + lane * 4]);
            acc.x += w4.x * r.x; acc.y += w4.x * r.y; acc.z += w4.x * r.z; acc.w += w4.x * r.w;
        }
        if (rem > 1) {
            float4 r = *reinterpret_cast<const float4*>(&g_HT[s4.y * BATCH + lane * 4]);
            acc.x += w4.y * r.x; acc.y += w4.y * r.y; acc.z += w4.y * r.z; acc.w += w4.y * r.w;
        }
        if (rem > 2) {
            float4 r = *reinterpret_cast<const float4*>(&g_HT[s4.z * BATCH + lane * 4]);
            acc.x += w4.z * r.x; acc.y += w4.z * r.y; acc.z += w4.z * r.z; acc.w += w4.z * r.w;
        }
        if (rem > 3) {
            float4 r = *reinterpret_cast<const float4*>(&g_HT[s4.w * BATCH + lane * 4]);
            acc.x += w4.w * r.x; acc.y += w4.w * r.y; acc.z += w4.w * r.z; acc.w += w4.w * r.w;
        }
    }
    *reinterpret_cast<float4*>(&red[warp][lane * 4]) = acc;
    __syncthreads();

    if (threadIdx.x < BATCH) {
        float v = 0.f;
        #pragma unroll
        for (int wq = 0; wq < 16; wq++) v += red[wq][threadIdx.x];
        out[threadIdx.x * OUT_F + o] = v;   // out[b][o]
    }
}

// ---------------------------------------------------------------------------
// Launch: 3 kernels (was 5)
// ---------------------------------------------------------------------------
extern "C" void kernel_launch(void* const* d_in, const int* in_sizes, int n_in,
                              void* d_out, int out_size) {
    const float* x       = (const float*)d_in[0];  // [128, 256]
    const float* w_in    = (const float*)d_in[1];  // [E_in]
    const float* w_ass   = (const float*)d_in[2];  // [E_ass]
    const int*   in_src  = (const int*)  d_in[3];
    const int*   in_dst  = (const int*)  d_in[4];
    const int*   ass_src = (const int*)  d_in[5];
    const int*   ass_dst = (const int*)  d_in[6];

    const int E_in  = in_sizes[1];
    const int E_ass = in_sizes[2];
    float* out = (float*)d_out;

    // Grid must cover: transpose (32768 threads), E_in/4, E_ass/4 edge groups.
    int threads_needed = BATCH * IN_F;                     // 32768
    int t1 = (E_in  + 3) / 4;
    int t2 = (E_ass + 3) / 4;
    if (t1 > threads_needed) threads_needed = t1;
    if (t2 > threads_needed) threads_needed = t2;
    int blocks = (threads_needed + 255) / 256;

    build_kernel<<<blocks, 256>>>(x, in_src, in_dst, w_in, E_in,
                                  ass_src, ass_dst, w_ass, E_ass);
    hop1_kernel <<<(N_ASS * 32) / 256, 256>>>();   // 512 CTAs, 1 warp/assoc
    hop2_kernel <<<OUT_F, 512>>>(out);             // 256 CTAs, 16 warps/output
}

// round 7
// speedup vs baseline: 1.9436x; 1.9024x over previous
#include <cuda_runtime.h>

// Problem constants (fixed by reference_code)
#define IN_F   256
#define N_ASS  4096
#define OUT_F  256
#define BATCH  128
#define ASS0   IN_F            // 256  : first associative neuron index
#define OUT0   (IN_F + N_ASS)  // 4352 : first output neuron index

// ELL strides (padded gather lists keyed by destination).
#define ELL1_S 64
#define ELL2_S 384

// Counter padding: 64 ints = 256B. The L2 slice hash uses addr bits {8,10-27}
// (bit 7 transparent), so 4B-contiguous counters all collapse onto ~4 LTS
// slice-groups and serialize the atomic ALU (R6: build=22us, issue=3.2%).
// 256B stride spreads the 52k slot-atomics across ~64 slice-groups.
#define CPAD 64

// Device scratch (no runtime allocation allowed). Zero-initialized at load;
// the hop kernels re-zero the counters after consuming them, so every graph
// replay sees counters == 0 on entry to the build kernel.
__device__ float g_xT  [IN_F  * BATCH];     // x transposed: [in_f][batch]
__device__ float g_HT  [N_ASS * BATCH];     // hidden acts transposed
__device__ int   g_cnt1[N_ASS * CPAD];      // padded per-assoc in-degree counters
__device__ int   g_cnt2[OUT_F * CPAD];      // padded per-output in-degree counters
__device__ int   g_e1src[N_ASS * ELL1_S];
__device__ float g_e1w  [N_ASS * ELL1_S];
__device__ int   g_e2src[OUT_F * ELL2_S];
__device__ float g_e2w  [OUT_F * ELL2_S];

// ---------------------------------------------------------------------------
// Kernel A (fused): transpose x -> xT, bucket hop1 edges (1 edge/thread,
// chain depth 1), bucket hop2 edges (int4 dst scan, keep only dst >= OUT0).
// ---------------------------------------------------------------------------
__global__ void __launch_bounds__(256)
build_kernel(const float* __restrict__ x,
             const int* __restrict__ in_src, const int* __restrict__ in_dst,
             const float* __restrict__ w_in, int E_in,
             const int* __restrict__ ass_src, const int* __restrict__ ass_dst,
             const float* __restrict__ w_ass, int E_ass) {
    const int t = blockIdx.x * blockDim.x + threadIdx.x;

    // --- transpose x (32768 elems) ---
    if (t < BATCH * IN_F) {
        int b = t >> 8;          // / IN_F
        int i = t & (IN_F - 1);  // % IN_F
        g_xT[i * BATCH + b] = x[t];
    }

    // --- hop1 bucketing: one edge per thread (single atomic chain) ---
    if (t < E_in) {
        int   d = in_dst[t] - ASS0;
        int   s = in_src[t];
        float w = w_in[t];
        int slot = atomicAdd(&g_cnt1[d * CPAD], 1);
        if (slot < ELL1_S) {
            g_e1src[d * ELL1_S + slot] = s;
            g_e1w  [d * ELL1_S + slot] = w;
        }
    }

    // --- hop2 bucketing: vectorized dst scan, lazy src/w fetch for kept ---
    const int e = t * 4;
    if (e + 4 <= E_ass) {
        int4 d4 = *reinterpret_cast<const int4*>(ass_dst + e);
        #pragma unroll
        for (int k = 0; k < 4; k++) {
            int d = (&d4.x)[k];
            if (d >= OUT0) {
                int o = d - OUT0;
                int slot = atomicAdd(&g_cnt2[o * CPAD], 1);
                if (slot < ELL2_S) {
                    g_e2src[o * ELL2_S + slot] = ass_src[e + k] - ASS0;
                    g_e2w  [o * ELL2_S + slot] = w_ass[e + k];
                }
            }
        }
    } else if (e < E_ass) {
        for (int k = e; k < E_ass; k++) {
            int d = ass_dst[k];
            if (d >= OUT0) {
                int o = d - OUT0;
                int slot = atomicAdd(&g_cnt2[o * CPAD], 1);
                if (slot < ELL2_S) {
                    g_e2src[o * ELL2_S + slot] = ass_src[k] - ASS0;
                    g_e2w  [o * ELL2_S + slot] = w_ass[k];
                }
            }
        }
    }
}

// ---------------------------------------------------------------------------
// Kernel B (hop 1): one warp per associative neuron.
// Edges consumed in aligned groups of 4 -> 4 independent 512B row gathers in
// flight (MLP=4). Resets its counter for the next graph replay.
// ---------------------------------------------------------------------------
__global__ void __launch_bounds__(256)
hop1_kernel() {
    const int warp = (blockIdx.x * blockDim.x + threadIdx.x) >> 5;  // 0..4095
    const int lane = threadIdx.x & 31;
    int deg = g_cnt1[warp * CPAD];
    __syncwarp();
    if (lane == 0) g_cnt1[warp * CPAD] = 0;   // consume-and-reset
    deg = min(deg, ELL1_S);
    const int base = warp * ELL1_S;           // multiple of 4 -> aligned groups

    float4 acc = make_float4(0.f, 0.f, 0.f, 0.f);
    int j = 0;
    for (; j + 4 <= deg; j += 4) {
        int4   s4 = *reinterpret_cast<const int4*>  (&g_e1src[base + j]);
        float4 w4 = *reinterpret_cast<const float4*>(&g_e1w  [base + j]);
        float4 r0 = *reinterpret_cast<const float4*>(&g_xT[s4.x * BATCH + lane * 4]);
        float4 r1 = *reinterpret_cast<const float4*>(&g_xT[s4.y * BATCH + lane * 4]);
        float4 r2 = *reinterpret_cast<const float4*>(&g_xT[s4.z * BATCH + lane * 4]);
        float4 r3 = *reinterpret_cast<const float4*>(&g_xT[s4.w * BATCH + lane * 4]);
        acc.x += w4.x * r0.x + w4.y * r1.x + w4.z * r2.x + w4.w * r3.x;
        acc.y += w4.x * r0.y + w4.y * r1.y + w4.z * r2.y + w4.w * r3.y;
        acc.z += w4.x * r0.z + w4.y * r1.z + w4.z * r2.z + w4.w * r3.z;
        acc.w += w4.x * r0.w + w4.y * r1.w + w4.z * r2.w + w4.w * r3.w;
    }
    for (; j < deg; j++) {
        int   s = g_e1src[base + j];
        float w = g_e1w  [base + j];
        float4 r = *reinterpret_cast<const float4*>(&g_xT[s * BATCH + lane * 4]);
        acc.x += w * r.x; acc.y += w * r.y; acc.z += w * r.z; acc.w += w * r.w;
    }
    *reinterpret_cast<float4*>(&g_HT[warp * BATCH + lane * 4]) = acc;
}

// ---------------------------------------------------------------------------
// Kernel C (hop 2): one CTA of 16 warps per output neuron.
// Warp g consumes aligned 4-edge groups: int4/float4 edge loads + 4
// independent HT row gathers. Smem tree-reduce, write out[b][o].
// Every out element written -> no zero pass. Resets its counter.
// ---------------------------------------------------------------------------
__global__ void __launch_bounds__(512)
hop2_kernel(float* __restrict__ out) {
    __shared__ float red[16][BATCH];
    const int o    = blockIdx.x;
    const int warp = threadIdx.x >> 5;
    const int lane = threadIdx.x & 31;
    int deg = min(g_cnt2[o * CPAD], ELL2_S);
    __syncthreads();                              // all reads of counter done
    if (threadIdx.x == 0) g_cnt2[o * CPAD] = 0;   // consume-and-reset
    const int base = o * ELL2_S;                  // multiple of 4

    float4 acc = make_float4(0.f, 0.f, 0.f, 0.f);
    for (int g = warp; ; g += 16) {
        int j = g * 4;
        if (j >= deg) break;
        int rem = deg - j;
        int4   s4 = *reinterpret_cast<const int4*>  (&g_e2src[base + j]);
        float4 w4 = *reinterpret_cast<const float4*>(&g_e2w  [base + j]);
        {
            float4 r = *reinterpret_cast<const float4*>(&g_HT[s4.x * BATCH + lane * 4]);
            acc.x += w4.x * r.x; acc.y += w4.x * r.y; acc.z += w4.x * r.z; acc.w += w4.x * r.w;
        }
        if (rem > 1) {
            float4 r = *reinterpret_cast<const float4*>(&g_HT[s4.y * BATCH + lane * 4]);
            acc.x += w4.y * r.x; acc.y += w4.y * r.y; acc.z += w4.y * r.z; acc.w += w4.y * r.w;
        }
        if (rem > 2) {
            float4 r = *reinterpret_cast<const float4*>(&g_HT[s4.z * BATCH + lane * 4]);
            acc.x += w4.z * r.x; acc.y += w4.z * r.y; acc.z += w4.z * r.z; acc.w += w4.z * r.w;
        }
        if (rem > 3) {
            float4 r = *reinterpret_cast<const float4*>(&g_HT[s4.w * BATCH + lane * 4]);
            acc.x += w4.w * r.x; acc.y += w4.w * r.y; acc.z += w4.w * r.z; acc.w += w4.w * r.w;
        }
    }
    *reinterpret_cast<float4*>(&red[warp][lane * 4]) = acc;
    __syncthreads();

    if (threadIdx.x < BATCH) {
        float v = 0.f;
        #pragma unroll
        for (int wq = 0; wq < 16; wq++) v += red[wq][threadIdx.x];
        out[threadIdx.x * OUT_F + o] = v;   // out[b][o]
    }
}

// ---------------------------------------------------------------------------
// Launch: 3 kernels
// ---------------------------------------------------------------------------
extern "C" void kernel_launch(void* const* d_in, const int* in_sizes, int n_in,
                              void* d_out, int out_size) {
    const float* x       = (const float*)d_in[0];  // [128, 256]
    const float* w_in    = (const float*)d_in[1];  // [E_in]
    const float* w_ass   = (const float*)d_in[2];  // [E_ass]
    const int*   in_src  = (const int*)  d_in[3];
    const int*   in_dst  = (const int*)  d_in[4];
    const int*   ass_src = (const int*)  d_in[5];
    const int*   ass_dst = (const int*)  d_in[6];

    const int E_in  = in_sizes[1];
    const int E_ass = in_sizes[2];
    float* out = (float*)d_out;

    // Grid covers: transpose (32768 threads), E_in edges, E_ass/4 edge groups.
    int threads_needed = BATCH * IN_F;              // 32768
    int t2 = (E_ass + 3) / 4;
    if (E_in > threads_needed) threads_needed = E_in;
    if (t2   > threads_needed) threads_needed = t2;
    int blocks = (threads_needed + 255) / 256;

    build_kernel<<<blocks, 256>>>(x, in_src, in_dst, w_in, E_in,
                                  ass_src, ass_dst, w_ass, E_ass);
    hop1_kernel <<<(N_ASS * 32) / 256, 256>>>();   // 512 CTAs, 1 warp/assoc
    hop2_kernel <<<OUT_F, 512>>>(out);             // 256 CTAs, 16 warps/output
}